// round 15
// baseline (speedup 1.0000x reference)
#include <cuda_runtime.h>
#include <cuda_fp16.h>
#include <math.h>
#include <stdint.h>

#define N_NODES 40962
#define DIM 512
#define N_EDGES 655392
#define NB 4
#define NHEADS 4
#define DH 128
#define CDIM 16
#define NFREQ 32

// ---------------- scratch (device globals; no allocation allowed) ----------------
__device__ __half g_qkv16[(size_t)N_NODES * 1536];   // packed q|k|v per node
__device__ __half g_y16[(size_t)N_NODES * DIM];
__device__ __half g_attn16[(size_t)N_NODES * DIM];
__device__ __half g_h16[(size_t)N_NODES * DIM];
__device__ __half g_cond16[(size_t)N_NODES * 32];    // cond(16) | 1.0 | zeros
__device__ __half g_film_t[32ull * 8192];            // FiLM tables, interleaved cols
__device__ float g_bqkv[4 * 1536];
__device__ int g_deg[N_NODES];
__device__ int g_rowptr[N_NODES + 1];
__device__ int g_cursor[N_NODES];
__device__ int g_csrdst[N_EDGES];
// weights transposed to [N,K] fp16.  24 slots = 4 blocks x {q,k,v,o,m1,m2}
__device__ __half g_wt[24ull * 512 * 512];

// ---------------- helpers ----------------
__device__ __forceinline__ uint32_t smem_u32(const void* p) {
    uint32_t a;
    asm("{ .reg .u64 t; cvta.to.shared.u64 t, %1; cvt.u32.u64 %0, t; }"
        : "=r"(a) : "l"(p));
    return a;
}

#define LDSM4(r, addr) \
    asm volatile("ldmatrix.sync.aligned.m8n8.x4.shared.b16 {%0,%1,%2,%3}, [%4];" \
        : "=r"((r)[0]), "=r"((r)[1]), "=r"((r)[2]), "=r"((r)[3]) : "r"(addr))

#define LDSM4T(r, addr) \
    asm volatile("ldmatrix.sync.aligned.m8n8.x4.trans.shared.b16 {%0,%1,%2,%3}, [%4];" \
        : "=r"((r)[0]), "=r"((r)[1]), "=r"((r)[2]), "=r"((r)[3]) : "r"(addr))

#define MMA16816(d, a, b0, b1) \
    asm volatile("mma.sync.aligned.m16n8k16.row.col.f32.f16.f16.f32 " \
        "{%0,%1,%2,%3}, {%4,%5,%6,%7}, {%8,%9}, {%0,%1,%2,%3};" \
        : "+f"((d)[0]), "+f"((d)[1]), "+f"((d)[2]), "+f"((d)[3]) \
        : "r"((a)[0]), "r"((a)[1]), "r"((a)[2]), "r"((a)[3]), "r"(b0), "r"(b1))

#define CP_ASYNC16(dst, src, sz) \
    asm volatile("cp.async.cg.shared.global [%0], [%1], 16, %2;" \
        :: "r"(dst), "l"(src), "r"(sz) : "memory")
#define CP_COMMIT() asm volatile("cp.async.commit_group;" ::: "memory")
#define CP_WAIT(N)  asm volatile("cp.async.wait_group %0;" :: "n"(N) : "memory")

// ---------------- Fourier noise embedding + cond MLP -> fp16 cond_ext --------------
__global__ void k_cond(const float* __restrict__ noise,
                       const float* __restrict__ fw1, const float* __restrict__ fb1,
                       const float* __restrict__ fw2, const float* __restrict__ fb2) {
    __shared__ float s_w1[2 * NFREQ * CDIM];
    __shared__ float s_w2[CDIM * CDIM];
    __shared__ float s_b1[CDIM];
    __shared__ float s_b2[CDIM];
    for (int i = threadIdx.x; i < 2 * NFREQ * CDIM; i += blockDim.x) s_w1[i] = fw1[i];
    for (int i = threadIdx.x; i < CDIM * CDIM; i += blockDim.x) s_w2[i] = fw2[i];
    if (threadIdx.x < CDIM) {
        s_b1[threadIdx.x] = fb1[threadIdx.x];
        s_b2[threadIdx.x] = fb2[threadIdx.x];
    }
    __syncthreads();
    int n = blockIdx.x * blockDim.x + threadIdx.x;
    if (n >= N_NODES) return;
    float t = noise[n];
    const float w0 = 2.0f * 3.14159265358979323846f / 16.0f;
    float emb[2 * NFREQ];
    #pragma unroll
    for (int f = 0; f < NFREQ; f++) {
        float ph = t * (w0 * (float)(f + 1));
        emb[f] = sinf(ph);
        emb[NFREQ + f] = cosf(ph);
    }
    float h[CDIM];
    #pragma unroll
    for (int c = 0; c < CDIM; c++) {
        float acc = s_b1[c];
        #pragma unroll
        for (int f = 0; f < 2 * NFREQ; f++) acc = fmaf(emb[f], s_w1[f * CDIM + c], acc);
        h[c] = acc / (1.0f + expf(-acc));
    }
    __half* out = g_cond16 + (size_t)n * 32;
    #pragma unroll
    for (int c2 = 0; c2 < CDIM; c2++) {
        float acc = s_b2[c2];
        #pragma unroll
        for (int c = 0; c < CDIM; c++) acc = fmaf(h[c], s_w2[c * CDIM + c2], acc);
        out[c2] = __float2half_rn(acc);
    }
    out[16] = __float2half_rn(1.0f);
    #pragma unroll
    for (int c2 = 17; c2 < 32; c2++) out[c2] = __float2half_rn(0.0f);
}

// ---------------- weight prep: transpose fp32 W[K,N] -> fp16 WT[N,K] ----------------
__global__ void k_prep_w(const float* __restrict__ wq, const float* __restrict__ wk,
                         const float* __restrict__ wv, const float* __restrict__ wo,
                         const float* __restrict__ w1, const float* __restrict__ w2) {
    int slot = blockIdx.z;
    int b = slot / 6, t = slot % 6;
    const float* W =
        (t == 0 ? wq : t == 1 ? wk : t == 2 ? wv : t == 3 ? wo : t == 4 ? w1 : w2) +
        (size_t)b * 512 * 512;
    __shared__ float tile[32][33];
    int x0 = blockIdx.x * 32, y0 = blockIdx.y * 32;
    int tx = threadIdx.x, ty = threadIdx.y;
    #pragma unroll
    for (int r = 0; r < 32; r += 8)
        tile[ty + r][tx] = W[(size_t)(y0 + ty + r) * 512 + x0 + tx];
    __syncthreads();
    size_t base = (size_t)slot * 512 * 512;
    #pragma unroll
    for (int r = 0; r < 32; r += 8) {
        float v = tile[tx][ty + r];
        g_wt[base + (size_t)(x0 + ty + r) * 512 + y0 + tx] = __float2half_rn(v);
    }
}

// ---------------- FiLM table build + packed qkv bias ----------------
// colout = b*2048 + ln*1024 + d*2 + which;  which=0 scale ("1+" folded), 1 bias
__global__ void k_film_tab(const float* __restrict__ s1w, const float* __restrict__ s1b,
                           const float* __restrict__ b1w, const float* __restrict__ b1b,
                           const float* __restrict__ s2w, const float* __restrict__ s2b,
                           const float* __restrict__ b2w, const float* __restrict__ b2b,
                           const float* __restrict__ bq, const float* __restrict__ bk,
                           const float* __restrict__ bv) {
    int idx = blockIdx.x * blockDim.x + threadIdx.x;
    if (idx < 32 * 8192) {
        int c = idx >> 13, colout = idx & 8191;
        int b = colout >> 11;
        int rem = colout & 2047;
        int ln = rem >> 10;
        int rem2 = rem & 1023;
        int d = rem2 >> 1, which = rem2 & 1;
        float v = 0.0f;
        if (c < 16) {
            const float* W = which == 0 ? (ln ? s2w : s1w) : (ln ? b2w : b1w);
            v = W[(size_t)b * CDIM * DIM + c * DIM + d];
        } else if (c == 16) {
            const float* Bv = which == 0 ? (ln ? s2b : s1b) : (ln ? b2b : b1b);
            v = Bv[b * DIM + d] + (which == 0 ? 1.0f : 0.0f);
        }
        g_film_t[(size_t)c * 8192 + colout] = __float2half_rn(v);
    } else {
        int bi = idx - 32 * 8192;
        if (bi < 4 * 1536) {
            int b = bi / 1536, j = bi % 1536;
            const float* src = j < 512 ? bq : (j < 1024 ? bk : bv);
            g_bqkv[b * 1536 + j] = src[b * 512 + (j & 511)];
        }
    }
}

// ---------------- CSR build ----------------
__global__ void k_zero_deg() {
    int i = blockIdx.x * blockDim.x + threadIdx.x;
    if (i < N_NODES) g_deg[i] = 0;
}

__global__ void k_count_deg(const int* __restrict__ edge) {
    int e = blockIdx.x * blockDim.x + threadIdx.x;
    if (e < N_EDGES) atomicAdd(&g_deg[edge[e]], 1);
}

__global__ void k_scan_deg() {
    __shared__ int partial[1024];
    const int tid = threadIdx.x;
    const int CH = (N_NODES + 1023) / 1024;
    const int base = tid * CH;
    int sum = 0;
    for (int i = 0; i < CH; i++) {
        int idx = base + i;
        if (idx < N_NODES) sum += g_deg[idx];
    }
    partial[tid] = sum;
    __syncthreads();
    for (int off = 1; off < 1024; off <<= 1) {
        int t = (tid >= off) ? partial[tid - off] : 0;
        __syncthreads();
        partial[tid] += t;
        __syncthreads();
    }
    int offset = (tid > 0) ? partial[tid - 1] : 0;
    for (int i = 0; i < CH; i++) {
        int idx = base + i;
        if (idx < N_NODES) {
            g_rowptr[idx] = offset;
            g_cursor[idx] = offset;
            offset += g_deg[idx];
        }
    }
    if (tid == 1023) g_rowptr[N_NODES] = partial[1023];
}

__global__ void k_scatter_edges(const int* __restrict__ edge) {
    int e = blockIdx.x * blockDim.x + threadIdx.x;
    if (e < N_EDGES) {
        int s = edge[e];
        int d = edge[N_EDGES + e];
        int p = atomicAdd(&g_cursor[s], 1);
        g_csrdst[p] = d;
    }
}

// ---------------- fused CLN + FiLM (R9 version: x-stash in smem) ------------------
#define SA_OFF 0
#define SB_OFF 10240
#define XB_OFF 76288
#define MU_OFF 209408
#define RV_OFF 209920
#define CLN_SMEM 210432

__global__ __launch_bounds__(512, 1) void k_cln_fused(const float* __restrict__ x,
                                                      int colbase) {
    extern __shared__ __align__(128) char sm[];
    const uint32_t sb_ = smem_u32(sm);
    const int tid = threadIdx.x, lane = tid & 31, wid = tid >> 5;
    const int row0 = blockIdx.x * 128;

    {
        int r = tid >> 2, q = tid & 3;
        uint32_t dst = sb_ + SA_OFF + (uint32_t)((r * 40 + q * 8) * 2);
        const __half* src = g_cond16 + (size_t)(row0 + r) * 32 + q * 8;
        CP_ASYNC16(dst, src, (row0 + r < N_NODES) ? 16 : 0);
    }
    #pragma unroll
    for (int i = 0; i < 8; i++) {
        int v = i * 512 + tid;
        int r = v >> 7, q = v & 127;
        uint32_t dst = sb_ + SB_OFF + (uint32_t)((r * 1032 + q * 8) * 2);
        const __half* src = g_film_t + (size_t)r * 8192 + colbase + q * 8;
        CP_ASYNC16(dst, src, 16);
    }
    CP_COMMIT();

    float* muP = (float*)(sm + MU_OFF);
    float* rvP = (float*)(sm + RV_OFF);
    __half* xb = (__half*)(sm + XB_OFF);
    #pragma unroll 1
    for (int it = 0; it < 8; it++) {
        int nl = it * 16 + wid;
        int n = row0 + nl;
        if (n < N_NODES) {
            float s = 0.f, s2 = 0.f;
            #pragma unroll
            for (int i = 0; i < 4; i++) {
                float4 xv = *(const float4*)(x + (size_t)n * 512 + lane * 4 + i * 128);
                s += xv.x + xv.y + xv.z + xv.w;
                s2 = fmaf(xv.x, xv.x, fmaf(xv.y, xv.y,
                     fmaf(xv.z, xv.z, fmaf(xv.w, xv.w, s2))));
                __half2 h01 = __floats2half2_rn(xv.x, xv.y);
                __half2 h23 = __floats2half2_rn(xv.z, xv.w);
                *(uint2*)(xb + nl * 520 + lane * 4 + i * 128) =
                    make_uint2(*(uint32_t*)&h01, *(uint32_t*)&h23);
            }
            #pragma unroll
            for (int o = 16; o; o >>= 1) {
                s += __shfl_xor_sync(0xffffffffu, s, o);
                s2 += __shfl_xor_sync(0xffffffffu, s2, o);
            }
            if (lane == 0) {
                float mu = s * (1.0f / DIM);
                float var = s2 * (1.0f / DIM) - mu * mu;
                muP[nl] = mu;
                rvP[nl] = rsqrtf(var + 1e-5f);
            }
        }
    }
    CP_WAIT(0);
    __syncthreads();

    const int aRow = lane & 15, aHi = lane >> 4;
    const int w = wid;
    #pragma unroll 1
    for (int mt = 0; mt < 8; mt++) {
        uint32_t ra[2][4];
        #pragma unroll
        for (int ks = 0; ks < 2; ks++)
            LDSM4(ra[ks], sb_ + SA_OFF +
                  (uint32_t)(((mt * 16 + aRow) * 40 + ks * 16 + aHi * 8) * 2));
        float acc[8][4];
        #pragma unroll
        for (int i = 0; i < 8; i++)
            #pragma unroll
            for (int r = 0; r < 4; r++) acc[i][r] = 0.0f;
        #pragma unroll
        for (int ks = 0; ks < 2; ks++) {
            #pragma unroll
            for (int bt = 0; bt < 4; bt++) {
                uint32_t rb[4];
                LDSM4T(rb, sb_ + SB_OFF +
                       (uint32_t)(((ks * 16 + aRow) * 1032 + w * 64 + bt * 16 + aHi * 8) * 2));
                MMA16816(acc[bt * 2 + 0], ra[ks], rb[0], rb[1]);
                MMA16816(acc[bt * 2 + 1], ra[ks], rb[2], rb[3]);
            }
        }
        #pragma unroll
        for (int h = 0; h < 2; h++) {
            int rl = mt * 16 + (lane >> 2) + h * 8;
            float muv = muP[rl], rv = rvP[rl];
            #pragma unroll
            for (int nt = 0; nt < 8; nt++) {
                int d = w * 32 + nt * 4 + (lane & 3);
                float xv = __half2float(xb[rl * 520 + d]);
                float y = (xv - muv) * rv * acc[nt][h * 2 + 0] + acc[nt][h * 2 + 1];
                xb[rl * 520 + d] = __float2half_rn(y);
            }
        }
    }
    __syncthreads();

    #pragma unroll
    for (int i = 0; i < 16; i++) {
        int v = i * 512 + tid;
        int r = v >> 6, q = v & 63;
        if (row0 + r < N_NODES)
            *(uint4*)(g_y16 + (size_t)(row0 + r) * 512 + q * 8) =
                *(uint4*)(xb + r * 520 + q * 8);
    }
}

// ---------------- HMMA GEMM: 128x128x64 tiles, 3-stage, 2 CTAs/SM ----------------
// flags: bit0 relu, bit1 residual(+Res fp32), bit2 fp16 out (to Ch, stride ldc)
#define SPITCH 72
#define AB_OFF (128 * SPITCH * 2)
#define STAGE_BYTES (256 * SPITCH * 2)
#define NSTAGE 3
#define GEMM_SMEM (NSTAGE * STAGE_BYTES)   // 110592 B; x2 CTAs = 216 KB/SM

__device__ __forceinline__ void g_load_stage(
    const __half* __restrict__ A, const __half* __restrict__ WT,
    uint32_t sbase, int row0, int k0, int M, int tid) {
    #pragma unroll
    for (int i = 0; i < 4; i++) {
        int v = i * 256 + tid;
        int r = v >> 3, q = v & 7;
        uint32_t dst = sbase + (uint32_t)(r * (SPITCH * 2) + q * 16);
        const __half* src = A + (size_t)(row0 + r) * 512 + k0 + q * 8;
        int sz = (row0 + r < M) ? 16 : 0;
        CP_ASYNC16(dst, src, sz);
    }
    #pragma unroll
    for (int i = 0; i < 4; i++) {
        int v = i * 256 + tid;
        int r = v >> 3, q = v & 7;
        uint32_t dst = sbase + AB_OFF + (uint32_t)(r * (SPITCH * 2) + q * 16);
        const __half* src = WT + (size_t)r * 512 + k0 + q * 8;
        CP_ASYNC16(dst, src, 16);
    }
    CP_COMMIT();
}

__global__ __launch_bounds__(256, 2) void k_gemm_hmma(
    const __half* __restrict__ A, int slot,
    const float* __restrict__ Bias, const float* __restrict__ Res,
    float* __restrict__ C, __half* __restrict__ Ch, int ldc, int M, int flags) {
    extern __shared__ __align__(128) char smem[];
    const int tid = threadIdx.x;
    const int lane = tid & 31, wid = tid >> 5;
    const int warpM = wid >> 2, warpN = wid & 3;   // 2 x 4
    const int col0 = blockIdx.x * 128, row0 = blockIdx.y * 128;
    const __half* WT = g_wt + (size_t)slot * 512 * 512 + (size_t)col0 * 512;
    const uint32_t sb = smem_u32(smem);

    float acc[4][4][4];
    #pragma unroll
    for (int i = 0; i < 4; i++)
        #pragma unroll
        for (int j = 0; j < 4; j++)
            #pragma unroll
            for (int r = 0; r < 4; r++) acc[i][j][r] = 0.0f;

    g_load_stage(A, WT, sb, row0, 0, M, tid);
    g_load_stage(A, WT, sb + STAGE_BYTES, row0, 64, M, tid);

    const int aRow = lane & 15, aHi = lane >> 4;
    #pragma unroll 1
    for (int it = 0; it < 8; it++) {
        if (it < 7) { CP_WAIT(1); } else { CP_WAIT(0); }
        __syncthreads();
        if (it < 6)
            g_load_stage(A, WT, sb + (uint32_t)((it + 2) % NSTAGE) * STAGE_BYTES,
                         row0, (it + 2) * 64, M, tid);

        uint32_t aB = sb + (uint32_t)(it % NSTAGE) * STAGE_BYTES;
        uint32_t bB = aB + AB_OFF;
        #pragma unroll
        for (int ks = 0; ks < 4; ks++) {
            uint32_t ra[4][4], rb[2][4];
            #pragma unroll
            for (int mt = 0; mt < 4; mt++) {
                uint32_t addr = aB +
                    (uint32_t)((warpM * 64 + mt * 16 + aRow) * (SPITCH * 2) +
                               ks * 32 + aHi * 16);
                LDSM4(ra[mt], addr);
            }
            #pragma unroll
            for (int bt = 0; bt < 2; bt++) {
                uint32_t addr = bB +
                    (uint32_t)((warpN * 32 + bt * 16 + aRow) * (SPITCH * 2) +
                               ks * 32 + aHi * 16);
                LDSM4(rb[bt], addr);
            }
            #pragma unroll
            for (int mt = 0; mt < 4; mt++) {
                #pragma unroll
                for (int bt = 0; bt < 2; bt++) {
                    MMA16816(acc[mt][bt * 2 + 0], ra[mt], rb[bt][0], rb[bt][2]);
                    MMA16816(acc[mt][bt * 2 + 1], ra[mt], rb[bt][1], rb[bt][3]);
                }
            }
        }
    }

    const bool relu = (flags & 1) != 0;
    const bool resid = (flags & 2) != 0;
    const bool half_out = (flags & 4) != 0;
    #pragma unroll
    for (int mt = 0; mt < 4; mt++) {
        #pragma unroll
        for (int nt = 0; nt < 4; nt++) {
            int gr = row0 + warpM * 64 + mt * 16 + (lane >> 2);
            int gc = col0 + warpN * 32 + (nt >> 1) * 16 + (nt & 1) * 8 + (lane & 3) * 2;
            float2 b2 = *(const float2*)(Bias + gc);
            #pragma unroll
            for (int h = 0; h < 2; h++) {
                int row = gr + h * 8;
                if (row >= M) continue;
                float v0 = acc[mt][nt][h * 2 + 0] + b2.x;
                float v1 = acc[mt][nt][h * 2 + 1] + b2.y;
                if (relu) { v0 = fmaxf(v0, 0.f); v1 = fmaxf(v1, 0.f); }
                if (resid) {
                    float2 rv = *(const float2*)(Res + (size_t)row * 512 + gc);
                    v0 += rv.x; v1 += rv.y;
                }
                if (half_out) {
                    __half2 hv = __floats2half2_rn(v0, v1);
                    *(__half2*)(Ch + (size_t)row * ldc + gc) = hv;
                } else {
                    *(float2*)(C + (size_t)row * 512 + gc) = make_float2(v0, v1);
                }
            }
        }
    }
}

// ---------------- sparse attention: pairwise-merged online softmax, __expf --------
__global__ void k_attn() {
    int n = blockIdx.x;
    int warp = threadIdx.x >> 5;
    int lane = threadIdx.x & 31;
    int beg = g_rowptr[n], end = g_rowptr[n + 1];
    const float scale = 0.08838834764831845f;   // 1/sqrt(128)
    int hoff = warp * DH + lane * 4;
    uint2 qu = *(const uint2*)&g_qkv16[(size_t)n * 1536 + hoff];
    float2 q01 = __half22float2(*(__half2*)&qu.x);
    float2 q23 = __half22float2(*(__half2*)&qu.y);
    float m = -INFINITY, s = 0.0f;
    float a0 = 0.f, a1 = 0.f, a2 = 0.f, a3 = 0.f;
    int koff = hoff + 512;
    int e = beg;
    for (; e + 2 <= end; e += 2) {
        int d0 = g_csrdst[e], d1 = g_csrdst[e + 1];
        const __half* r0 = g_qkv16 + (size_t)d0 * 1536 + koff;
        const __half* r1 = g_qkv16 + (size_t)d1 * 1536 + koff;
        uint2 k0u = *(const uint2*)r0;
        uint2 k1u = *(const uint2*)r1;
        uint2 v0u = *(const uint2*)(r0 + 512);
        uint2 v1u = *(const uint2*)(r1 + 512);
        float2 k01 = __half22float2(*(__half2*)&k0u.x);
        float2 k23 = __half22float2(*(__half2*)&k0u.y);
        float p0 = q01.x * k01.x + q01.y * k01.y + q23.x * k23.x + q23.y * k23.y;
        float2 l01 = __half22float2(*(__half2*)&k1u.x);
        float2 l23 = __half22float2(*(__half2*)&k1u.y);
        float p1 = q01.x * l01.x + q01.y * l01.y + q23.x * l23.x + q23.y * l23.y;
        #pragma unroll
        for (int o = 16; o; o >>= 1) {
            p0 += __shfl_xor_sync(0xffffffffu, p0, o);
            p1 += __shfl_xor_sync(0xffffffffu, p1, o);
        }
        p0 *= scale; p1 *= scale;
        float mn = fmaxf(m, fmaxf(p0, p1));
        float corr = __expf(m - mn);
        float w0 = __expf(p0 - mn);
        float w1 = __expf(p1 - mn);
        float2 v01 = __half22float2(*(__half2*)&v0u.x);
        float2 v23 = __half22float2(*(__half2*)&v0u.y);
        float2 u01 = __half22float2(*(__half2*)&v1u.x);
        float2 u23 = __half22float2(*(__half2*)&v1u.y);
        s = s * corr + w0 + w1;
        a0 = fmaf(w0, v01.x, fmaf(w1, u01.x, a0 * corr));
        a1 = fmaf(w0, v01.y, fmaf(w1, u01.y, a1 * corr));
        a2 = fmaf(w0, v23.x, fmaf(w1, u23.x, a2 * corr));
        a3 = fmaf(w0, v23.y, fmaf(w1, u23.y, a3 * corr));
        m = mn;
    }
    if (e < end) {
        int d = g_csrdst[e];
        const __half* r0 = g_qkv16 + (size_t)d * 1536 + koff;
        uint2 ku = *(const uint2*)r0;
        uint2 vu = *(const uint2*)(r0 + 512);
        float2 k01 = __half22float2(*(__half2*)&ku.x);
        float2 k23 = __half22float2(*(__half2*)&ku.y);
        float p = q01.x * k01.x + q01.y * k01.y + q23.x * k23.x + q23.y * k23.y;
        #pragma unroll
        for (int o = 16; o; o >>= 1) p += __shfl_xor_sync(0xffffffffu, p, o);
        p *= scale;
        float mn = fmaxf(m, p);
        float corr = __expf(m - mn);
        float w = __expf(p - mn);
        float2 v01 = __half22float2(*(__half2*)&vu.x);
        float2 v23 = __half22float2(*(__half2*)&vu.y);
        s = s * corr + w;
        a0 = fmaf(w, v01.x, a0 * corr);
        a1 = fmaf(w, v01.y, a1 * corr);
        a2 = fmaf(w, v23.x, a2 * corr);
        a3 = fmaf(w, v23.y, a3 * corr);
        m = mn;
    }
    float inv = (end > beg) ? (1.0f / s) : 0.0f;
    __half2 h01 = __floats2half2_rn(a0 * inv, a1 * inv);
    __half2 h23 = __floats2half2_rn(a2 * inv, a3 * inv);
    *(uint2*)(g_attn16 + (size_t)n * DIM + hoff) =
        make_uint2(*(uint32_t*)&h01, *(uint32_t*)&h23);
}

// ---------------- host ----------------
extern "C" void kernel_launch(void* const* d_in, const int* in_sizes, int n_in,
                              void* d_out, int out_size) {
    const float* x_in  = (const float*)d_in[0];
    const int*   edge  = (const int*)d_in[1];
    const float* noise = (const float*)d_in[2];
    const float* f_w1 = (const float*)d_in[3];
    const float* f_b1 = (const float*)d_in[4];
    const float* f_w2 = (const float*)d_in[5];
    const float* f_b2 = (const float*)d_in[6];
    const float* s1_w = (const float*)d_in[7];
    const float* s1_b = (const float*)d_in[8];
    const float* b1_w = (const float*)d_in[9];
    const float* b1_b = (const float*)d_in[10];
    const float* wq = (const float*)d_in[11];
    const float* bq = (const float*)d_in[12];
    const float* wk = (const float*)d_in[13];
    const float* bk = (const float*)d_in[14];
    const float* wv = (const float*)d_in[15];
    const float* bv = (const float*)d_in[16];
    const float* wo = (const float*)d_in[17];
    const float* bo = (const float*)d_in[18];
    const float* s2_w = (const float*)d_in[19];
    const float* s2_b = (const float*)d_in[20];
    const float* b2_w = (const float*)d_in[21];
    const float* b2_b = (const float*)d_in[22];
    const float* m_w1 = (const float*)d_in[23];
    const float* m_b1 = (const float*)d_in[24];
    const float* m_w2 = (const float*)d_in[25];
    const float* m_b2 = (const float*)d_in[26];

    float* x = (float*)d_out;

    static bool init_done = false;
    static cudaStream_t s1;
    static cudaEvent_t evFork, evTab, evPrep, evCsr;
    if (!init_done) {
        cudaFuncSetAttribute(k_gemm_hmma, cudaFuncAttributeMaxDynamicSharedMemorySize,
                             GEMM_SMEM);
        cudaFuncSetAttribute(k_cln_fused, cudaFuncAttributeMaxDynamicSharedMemorySize,
                             CLN_SMEM);
        cudaStreamCreateWithFlags(&s1, cudaStreamNonBlocking);
        cudaEventCreateWithFlags(&evFork, cudaEventDisableTiming);
        cudaEventCreateWithFlags(&evTab, cudaEventDisableTiming);
        cudaEventCreateWithFlags(&evPrep, cudaEventDisableTiming);
        cudaEventCreateWithFlags(&evCsr, cudaEventDisableTiming);
        init_done = true;
    }

    __half *qkv16, *yp16, *ap16, *hp16;
    float *bqkv;
    cudaGetSymbolAddress((void**)&qkv16, g_qkv16);
    cudaGetSymbolAddress((void**)&yp16, g_y16);
    cudaGetSymbolAddress((void**)&ap16, g_attn16);
    cudaGetSymbolAddress((void**)&hp16, g_h16);
    cudaGetSymbolAddress((void**)&bqkv, g_bqkv);

    // ---- fork side stream for setup work (capture-legal fork/join) ----
    cudaEventRecord(evFork, 0);
    cudaStreamWaitEvent(s1, evFork, 0);

    // s1: FiLM tables, weight prep, CSR build
    k_film_tab<<<(32 * 8192 + 4 * 1536 + 255) / 256, 256, 0, s1>>>(
        s1_w, s1_b, b1_w, b1_b, s2_w, s2_b, b2_w, b2_b, bq, bk, bv);
    cudaEventRecord(evTab, s1);
    k_prep_w<<<dim3(16, 16, 24), dim3(32, 8), 0, s1>>>(wq, wk, wv, wo, m_w1, m_w2);
    cudaEventRecord(evPrep, s1);
    k_zero_deg<<<(N_NODES + 255) / 256, 256, 0, s1>>>();
    k_count_deg<<<(N_EDGES + 255) / 256, 256, 0, s1>>>(edge);
    k_scan_deg<<<1, 1024, 0, s1>>>();
    k_scatter_edges<<<(N_EDGES + 255) / 256, 256, 0, s1>>>(edge);
    cudaEventRecord(evCsr, s1);

    // s0: conditioning (independent of s1 work)
    k_cond<<<(N_NODES + 127) / 128, 128>>>(noise, f_w1, f_b1, f_w2, f_b2);

    const int CGRID = (N_NODES + 127) / 128;   // 321
    const int MROWS = (N_NODES + 127) / 128;
    dim3 gq(12, MROWS);
    dim3 gg(4, MROWS);
    bool waited_tab = false, waited_prep = false, waited_csr = false;
    for (int b = 0; b < NB; b++) {
        const size_t bOff = (size_t)b * DIM;
        const int slot = b * 6;
        const float* xr = (b == 0) ? x_in : x;

        if (!waited_tab) { cudaStreamWaitEvent(0, evTab, 0); waited_tab = true; }
        k_cln_fused<<<CGRID, 512, CLN_SMEM>>>(xr, b * 2048 + 0);
        if (!waited_prep) { cudaStreamWaitEvent(0, evPrep, 0); waited_prep = true; }
        k_gemm_hmma<<<gq, 256, GEMM_SMEM>>>(yp16, slot, bqkv + b * 1536, nullptr,
                                            nullptr, qkv16, 1536, N_NODES, 4);
        if (!waited_csr) { cudaStreamWaitEvent(0, evCsr, 0); waited_csr = true; }
        k_attn<<<N_NODES, 128>>>();
        k_gemm_hmma<<<gg, 256, GEMM_SMEM>>>(ap16, slot + 3, bo + bOff, xr, x,
                                            nullptr, 512, N_NODES, 2);
        k_cln_fused<<<CGRID, 512, CLN_SMEM>>>(x, b * 2048 + 1024);
        k_gemm_hmma<<<gg, 256, GEMM_SMEM>>>(yp16, slot + 4, m_b1 + bOff, nullptr,
                                            nullptr, hp16, 512, N_NODES, 5);
        k_gemm_hmma<<<gg, 256, GEMM_SMEM>>>(hp16, slot + 5, m_b2 + bOff, x, x,
                                            nullptr, 512, N_NODES, 2);
    }
}

// round 16
// speedup vs baseline: 1.0247x; 1.0247x over previous
#include <cuda_runtime.h>
#include <cuda_fp16.h>
#include <math.h>
#include <stdint.h>

#define N_NODES 40962
#define DIM 512
#define N_EDGES 655392
#define NB 4
#define NHEADS 4
#define DH 128
#define CDIM 16
#define NFREQ 32

// ---------------- scratch (device globals; no allocation allowed) ----------------
__device__ __half g_qkv16[(size_t)N_NODES * 1536];   // packed q|k|v per node
__device__ __half g_y16[(size_t)N_NODES * DIM];
__device__ __half g_attn16[(size_t)N_NODES * DIM];
__device__ __half g_h16[(size_t)N_NODES * DIM];
__device__ __half g_cond16[(size_t)N_NODES * 32];    // cond(16) | 1.0 | zeros
__device__ __half g_film_t[32ull * 8192];            // FiLM tables, interleaved cols
__device__ float g_bqkv[4 * 1536];
__device__ int g_deg[N_NODES];
__device__ int g_rowptr[N_NODES + 1];
__device__ int g_cursor[N_NODES];
__device__ int g_csrdst[N_EDGES];
// weights transposed to [N,K] fp16.  24 slots = 4 blocks x {q,k,v,o,m1,m2}
__device__ __half g_wt[24ull * 512 * 512];

// ---------------- helpers ----------------
__device__ __forceinline__ uint32_t smem_u32(const void* p) {
    uint32_t a;
    asm("{ .reg .u64 t; cvta.to.shared.u64 t, %1; cvt.u32.u64 %0, t; }"
        : "=r"(a) : "l"(p));
    return a;
}

#define LDSM4(r, addr) \
    asm volatile("ldmatrix.sync.aligned.m8n8.x4.shared.b16 {%0,%1,%2,%3}, [%4];" \
        : "=r"((r)[0]), "=r"((r)[1]), "=r"((r)[2]), "=r"((r)[3]) : "r"(addr))

#define LDSM4T(r, addr) \
    asm volatile("ldmatrix.sync.aligned.m8n8.x4.trans.shared.b16 {%0,%1,%2,%3}, [%4];" \
        : "=r"((r)[0]), "=r"((r)[1]), "=r"((r)[2]), "=r"((r)[3]) : "r"(addr))

#define MMA16816(d, a, b0, b1) \
    asm volatile("mma.sync.aligned.m16n8k16.row.col.f32.f16.f16.f32 " \
        "{%0,%1,%2,%3}, {%4,%5,%6,%7}, {%8,%9}, {%0,%1,%2,%3};" \
        : "+f"((d)[0]), "+f"((d)[1]), "+f"((d)[2]), "+f"((d)[3]) \
        : "r"((a)[0]), "r"((a)[1]), "r"((a)[2]), "r"((a)[3]), "r"(b0), "r"(b1))

#define CP_ASYNC16(dst, src, sz) \
    asm volatile("cp.async.cg.shared.global [%0], [%1], 16, %2;" \
        :: "r"(dst), "l"(src), "r"(sz) : "memory")
#define CP_COMMIT() asm volatile("cp.async.commit_group;" ::: "memory")
#define CP_WAIT(N)  asm volatile("cp.async.wait_group %0;" :: "n"(N) : "memory")

// ---------------- Fourier noise embedding + cond MLP -> fp16 cond_ext --------------
__global__ void k_cond(const float* __restrict__ noise,
                       const float* __restrict__ fw1, const float* __restrict__ fb1,
                       const float* __restrict__ fw2, const float* __restrict__ fb2) {
    __shared__ float s_w1[2 * NFREQ * CDIM];
    __shared__ float s_w2[CDIM * CDIM];
    __shared__ float s_b1[CDIM];
    __shared__ float s_b2[CDIM];
    for (int i = threadIdx.x; i < 2 * NFREQ * CDIM; i += blockDim.x) s_w1[i] = fw1[i];
    for (int i = threadIdx.x; i < CDIM * CDIM; i += blockDim.x) s_w2[i] = fw2[i];
    if (threadIdx.x < CDIM) {
        s_b1[threadIdx.x] = fb1[threadIdx.x];
        s_b2[threadIdx.x] = fb2[threadIdx.x];
    }
    __syncthreads();
    int n = blockIdx.x * blockDim.x + threadIdx.x;
    if (n >= N_NODES) return;
    float t = noise[n];
    const float w0 = 2.0f * 3.14159265358979323846f / 16.0f;
    float emb[2 * NFREQ];
    #pragma unroll
    for (int f = 0; f < NFREQ; f++) {
        float ph = t * (w0 * (float)(f + 1));
        emb[f] = sinf(ph);
        emb[NFREQ + f] = cosf(ph);
    }
    float h[CDIM];
    #pragma unroll
    for (int c = 0; c < CDIM; c++) {
        float acc = s_b1[c];
        #pragma unroll
        for (int f = 0; f < 2 * NFREQ; f++) acc = fmaf(emb[f], s_w1[f * CDIM + c], acc);
        h[c] = acc / (1.0f + expf(-acc));
    }
    __half* out = g_cond16 + (size_t)n * 32;
    #pragma unroll
    for (int c2 = 0; c2 < CDIM; c2++) {
        float acc = s_b2[c2];
        #pragma unroll
        for (int c = 0; c < CDIM; c++) acc = fmaf(h[c], s_w2[c * CDIM + c2], acc);
        out[c2] = __float2half_rn(acc);
    }
    out[16] = __float2half_rn(1.0f);
    #pragma unroll
    for (int c2 = 17; c2 < 32; c2++) out[c2] = __float2half_rn(0.0f);
}

// ---------------- weight prep: transpose fp32 W[K,N] -> fp16 WT[N,K] ----------------
__global__ void k_prep_w(const float* __restrict__ wq, const float* __restrict__ wk,
                         const float* __restrict__ wv, const float* __restrict__ wo,
                         const float* __restrict__ w1, const float* __restrict__ w2) {
    int slot = blockIdx.z;
    int b = slot / 6, t = slot % 6;
    const float* W =
        (t == 0 ? wq : t == 1 ? wk : t == 2 ? wv : t == 3 ? wo : t == 4 ? w1 : w2) +
        (size_t)b * 512 * 512;
    __shared__ float tile[32][33];
    int x0 = blockIdx.x * 32, y0 = blockIdx.y * 32;
    int tx = threadIdx.x, ty = threadIdx.y;
    #pragma unroll
    for (int r = 0; r < 32; r += 8)
        tile[ty + r][tx] = W[(size_t)(y0 + ty + r) * 512 + x0 + tx];
    __syncthreads();
    size_t base = (size_t)slot * 512 * 512;
    #pragma unroll
    for (int r = 0; r < 32; r += 8) {
        float v = tile[tx][ty + r];
        g_wt[base + (size_t)(x0 + ty + r) * 512 + y0 + tx] = __float2half_rn(v);
    }
}

// ---------------- FiLM table build + packed qkv bias ----------------
// colout = b*2048 + ln*1024 + d*2 + which;  which=0 scale ("1+" folded), 1 bias
__global__ void k_film_tab(const float* __restrict__ s1w, const float* __restrict__ s1b,
                           const float* __restrict__ b1w, const float* __restrict__ b1b,
                           const float* __restrict__ s2w, const float* __restrict__ s2b,
                           const float* __restrict__ b2w, const float* __restrict__ b2b,
                           const float* __restrict__ bq, const float* __restrict__ bk,
                           const float* __restrict__ bv) {
    int idx = blockIdx.x * blockDim.x + threadIdx.x;
    if (idx < 32 * 8192) {
        int c = idx >> 13, colout = idx & 8191;
        int b = colout >> 11;
        int rem = colout & 2047;
        int ln = rem >> 10;
        int rem2 = rem & 1023;
        int d = rem2 >> 1, which = rem2 & 1;
        float v = 0.0f;
        if (c < 16) {
            const float* W = which == 0 ? (ln ? s2w : s1w) : (ln ? b2w : b1w);
            v = W[(size_t)b * CDIM * DIM + c * DIM + d];
        } else if (c == 16) {
            const float* Bv = which == 0 ? (ln ? s2b : s1b) : (ln ? b2b : b1b);
            v = Bv[b * DIM + d] + (which == 0 ? 1.0f : 0.0f);
        }
        g_film_t[(size_t)c * 8192 + colout] = __float2half_rn(v);
    } else {
        int bi = idx - 32 * 8192;
        if (bi < 4 * 1536) {
            int b = bi / 1536, j = bi % 1536;
            const float* src = j < 512 ? bq : (j < 1024 ? bk : bv);
            g_bqkv[b * 1536 + j] = src[b * 512 + (j & 511)];
        }
    }
}

// ---------------- CSR build ----------------
__global__ void k_zero_deg() {
    int i = blockIdx.x * blockDim.x + threadIdx.x;
    if (i < N_NODES) g_deg[i] = 0;
}

__global__ void k_count_deg(const int* __restrict__ edge) {
    int e = blockIdx.x * blockDim.x + threadIdx.x;
    if (e < N_EDGES) atomicAdd(&g_deg[edge[e]], 1);
}

__global__ void k_scan_deg() {
    __shared__ int partial[1024];
    const int tid = threadIdx.x;
    const int CH = (N_NODES + 1023) / 1024;
    const int base = tid * CH;
    int sum = 0;
    for (int i = 0; i < CH; i++) {
        int idx = base + i;
        if (idx < N_NODES) sum += g_deg[idx];
    }
    partial[tid] = sum;
    __syncthreads();
    for (int off = 1; off < 1024; off <<= 1) {
        int t = (tid >= off) ? partial[tid - off] : 0;
        __syncthreads();
        partial[tid] += t;
        __syncthreads();
    }
    int offset = (tid > 0) ? partial[tid - 1] : 0;
    for (int i = 0; i < CH; i++) {
        int idx = base + i;
        if (idx < N_NODES) {
            g_rowptr[idx] = offset;
            g_cursor[idx] = offset;
            offset += g_deg[idx];
        }
    }
    if (tid == 1023) g_rowptr[N_NODES] = partial[1023];
}

__global__ void k_scatter_edges(const int* __restrict__ edge) {
    int e = blockIdx.x * blockDim.x + threadIdx.x;
    if (e < N_EDGES) {
        int s = edge[e];
        int d = edge[N_EDGES + e];
        int p = atomicAdd(&g_cursor[s], 1);
        g_csrdst[p] = d;
    }
}

// ---------------- fused CLN + FiLM (x-stash in smem) ------------------------------
#define SA_OFF 0
#define SB_OFF 10240
#define XB_OFF 76288
#define MU_OFF 209408
#define RV_OFF 209920
#define CLN_SMEM 210432

__global__ __launch_bounds__(512, 1) void k_cln_fused(const float* __restrict__ x,
                                                      int colbase) {
    extern __shared__ __align__(128) char sm[];
    const uint32_t sb_ = smem_u32(sm);
    const int tid = threadIdx.x, lane = tid & 31, wid = tid >> 5;
    const int row0 = blockIdx.x * 128;

    {
        int r = tid >> 2, q = tid & 3;
        uint32_t dst = sb_ + SA_OFF + (uint32_t)((r * 40 + q * 8) * 2);
        const __half* src = g_cond16 + (size_t)(row0 + r) * 32 + q * 8;
        CP_ASYNC16(dst, src, (row0 + r < N_NODES) ? 16 : 0);
    }
    #pragma unroll
    for (int i = 0; i < 8; i++) {
        int v = i * 512 + tid;
        int r = v >> 7, q = v & 127;
        uint32_t dst = sb_ + SB_OFF + (uint32_t)((r * 1032 + q * 8) * 2);
        const __half* src = g_film_t + (size_t)r * 8192 + colbase + q * 8;
        CP_ASYNC16(dst, src, 16);
    }
    CP_COMMIT();

    float* muP = (float*)(sm + MU_OFF);
    float* rvP = (float*)(sm + RV_OFF);
    __half* xb = (__half*)(sm + XB_OFF);
    #pragma unroll 1
    for (int it = 0; it < 8; it++) {
        int nl = it * 16 + wid;
        int n = row0 + nl;
        if (n < N_NODES) {
            float s = 0.f, s2 = 0.f;
            #pragma unroll
            for (int i = 0; i < 4; i++) {
                float4 xv = *(const float4*)(x + (size_t)n * 512 + lane * 4 + i * 128);
                s += xv.x + xv.y + xv.z + xv.w;
                s2 = fmaf(xv.x, xv.x, fmaf(xv.y, xv.y,
                     fmaf(xv.z, xv.z, fmaf(xv.w, xv.w, s2))));
                __half2 h01 = __floats2half2_rn(xv.x, xv.y);
                __half2 h23 = __floats2half2_rn(xv.z, xv.w);
                *(uint2*)(xb + nl * 520 + lane * 4 + i * 128) =
                    make_uint2(*(uint32_t*)&h01, *(uint32_t*)&h23);
            }
            #pragma unroll
            for (int o = 16; o; o >>= 1) {
                s += __shfl_xor_sync(0xffffffffu, s, o);
                s2 += __shfl_xor_sync(0xffffffffu, s2, o);
            }
            if (lane == 0) {
                float mu = s * (1.0f / DIM);
                float var = s2 * (1.0f / DIM) - mu * mu;
                muP[nl] = mu;
                rvP[nl] = rsqrtf(var + 1e-5f);
            }
        }
    }
    CP_WAIT(0);
    __syncthreads();

    const int aRow = lane & 15, aHi = lane >> 4;
    const int w = wid;
    #pragma unroll 1
    for (int mt = 0; mt < 8; mt++) {
        uint32_t ra[2][4];
        #pragma unroll
        for (int ks = 0; ks < 2; ks++)
            LDSM4(ra[ks], sb_ + SA_OFF +
                  (uint32_t)(((mt * 16 + aRow) * 40 + ks * 16 + aHi * 8) * 2));
        float acc[8][4];
        #pragma unroll
        for (int i = 0; i < 8; i++)
            #pragma unroll
            for (int r = 0; r < 4; r++) acc[i][r] = 0.0f;
        #pragma unroll
        for (int ks = 0; ks < 2; ks++) {
            #pragma unroll
            for (int bt = 0; bt < 4; bt++) {
                uint32_t rb[4];
                LDSM4T(rb, sb_ + SB_OFF +
                       (uint32_t)(((ks * 16 + aRow) * 1032 + w * 64 + bt * 16 + aHi * 8) * 2));
                MMA16816(acc[bt * 2 + 0], ra[ks], rb[0], rb[1]);
                MMA16816(acc[bt * 2 + 1], ra[ks], rb[2], rb[3]);
            }
        }
        #pragma unroll
        for (int h = 0; h < 2; h++) {
            int rl = mt * 16 + (lane >> 2) + h * 8;
            float muv = muP[rl], rv = rvP[rl];
            #pragma unroll
            for (int nt = 0; nt < 8; nt++) {
                int d = w * 32 + nt * 4 + (lane & 3);
                float xv = __half2float(xb[rl * 520 + d]);
                float y = (xv - muv) * rv * acc[nt][h * 2 + 0] + acc[nt][h * 2 + 1];
                xb[rl * 520 + d] = __float2half_rn(y);
            }
        }
    }
    __syncthreads();

    #pragma unroll
    for (int i = 0; i < 16; i++) {
        int v = i * 512 + tid;
        int r = v >> 6, q = v & 63;
        if (row0 + r < N_NODES)
            *(uint4*)(g_y16 + (size_t)(row0 + r) * 512 + q * 8) =
                *(uint4*)(xb + r * 520 + q * 8);
    }
}

// ---------------- HMMA GEMM: 128x128x64 tiles, 2-stage, 2 CTAs/SM ----------------
// flags: bit0 relu, bit1 residual(+Res fp32), bit2 fp16 out (to Ch, stride ldc)
#define SPITCH 72
#define AB_OFF (128 * SPITCH * 2)
#define STAGE_BYTES (256 * SPITCH * 2)
#define NSTAGE 2
#define GEMM_SMEM (NSTAGE * STAGE_BYTES)

__device__ __forceinline__ void g_load_stage(
    const __half* __restrict__ A, const __half* __restrict__ WT,
    uint32_t sbase, int row0, int k0, int M, int tid) {
    #pragma unroll
    for (int i = 0; i < 4; i++) {
        int v = i * 256 + tid;
        int r = v >> 3, q = v & 7;
        uint32_t dst = sbase + (uint32_t)(r * (SPITCH * 2) + q * 16);
        const __half* src = A + (size_t)(row0 + r) * 512 + k0 + q * 8;
        int sz = (row0 + r < M) ? 16 : 0;
        CP_ASYNC16(dst, src, sz);
    }
    #pragma unroll
    for (int i = 0; i < 4; i++) {
        int v = i * 256 + tid;
        int r = v >> 3, q = v & 7;
        uint32_t dst = sbase + AB_OFF + (uint32_t)(r * (SPITCH * 2) + q * 16);
        const __half* src = WT + (size_t)r * 512 + k0 + q * 8;
        CP_ASYNC16(dst, src, 16);
    }
    CP_COMMIT();
}

__global__ __launch_bounds__(256, 2) void k_gemm_hmma(
    const __half* __restrict__ A, int slot,
    const float* __restrict__ Bias, const float* __restrict__ Res,
    float* __restrict__ C, __half* __restrict__ Ch, int ldc, int M, int flags) {
    extern __shared__ __align__(128) char smem[];
    const int tid = threadIdx.x;
    const int lane = tid & 31, wid = tid >> 5;
    const int warpM = wid >> 2, warpN = wid & 3;   // 2 x 4
    const int col0 = blockIdx.x * 128, row0 = blockIdx.y * 128;
    const __half* WT = g_wt + (size_t)slot * 512 * 512 + (size_t)col0 * 512;
    const uint32_t sb = smem_u32(smem);

    float acc[4][4][4];
    #pragma unroll
    for (int i = 0; i < 4; i++)
        #pragma unroll
        for (int j = 0; j < 4; j++)
            #pragma unroll
            for (int r = 0; r < 4; r++) acc[i][j][r] = 0.0f;

    g_load_stage(A, WT, sb, row0, 0, M, tid);

    const int aRow = lane & 15, aHi = lane >> 4;
    #pragma unroll 1
    for (int it = 0; it < 8; it++) {
        CP_WAIT(0);
        __syncthreads();
        if (it < 7)
            g_load_stage(A, WT, sb + (uint32_t)((it + 1) & 1) * STAGE_BYTES,
                         row0, (it + 1) * 64, M, tid);

        uint32_t aB = sb + (uint32_t)(it & 1) * STAGE_BYTES;
        uint32_t bB = aB + AB_OFF;
        #pragma unroll
        for (int ks = 0; ks < 4; ks++) {
            uint32_t ra[4][4], rb[2][4];
            #pragma unroll
            for (int mt = 0; mt < 4; mt++) {
                uint32_t addr = aB +
                    (uint32_t)((warpM * 64 + mt * 16 + aRow) * (SPITCH * 2) +
                               ks * 32 + aHi * 16);
                LDSM4(ra[mt], addr);
            }
            #pragma unroll
            for (int bt = 0; bt < 2; bt++) {
                uint32_t addr = bB +
                    (uint32_t)((warpN * 32 + bt * 16 + aRow) * (SPITCH * 2) +
                               ks * 32 + aHi * 16);
                LDSM4(rb[bt], addr);
            }
            #pragma unroll
            for (int mt = 0; mt < 4; mt++) {
                #pragma unroll
                for (int bt = 0; bt < 2; bt++) {
                    MMA16816(acc[mt][bt * 2 + 0], ra[mt], rb[bt][0], rb[bt][2]);
                    MMA16816(acc[mt][bt * 2 + 1], ra[mt], rb[bt][1], rb[bt][3]);
                }
            }
        }
    }

    const bool relu = (flags & 1) != 0;
    const bool resid = (flags & 2) != 0;
    const bool half_out = (flags & 4) != 0;
    #pragma unroll
    for (int mt = 0; mt < 4; mt++) {
        #pragma unroll
        for (int nt = 0; nt < 4; nt++) {
            int gr = row0 + warpM * 64 + mt * 16 + (lane >> 2);
            int gc = col0 + warpN * 32 + (nt >> 1) * 16 + (nt & 1) * 8 + (lane & 3) * 2;
            float2 b2 = *(const float2*)(Bias + gc);
            #pragma unroll
            for (int h = 0; h < 2; h++) {
                int row = gr + h * 8;
                if (row >= M) continue;
                float v0 = acc[mt][nt][h * 2 + 0] + b2.x;
                float v1 = acc[mt][nt][h * 2 + 1] + b2.y;
                if (relu) { v0 = fmaxf(v0, 0.f); v1 = fmaxf(v1, 0.f); }
                if (resid) {
                    float2 rv = *(const float2*)(Res + (size_t)row * 512 + gc);
                    v0 += rv.x; v1 += rv.y;
                }
                if (half_out) {
                    __half2 hv = __floats2half2_rn(v0, v1);
                    *(__half2*)(Ch + (size_t)row * ldc + gc) = hv;
                } else {
                    *(float2*)(C + (size_t)row * 512 + gc) = make_float2(v0, v1);
                }
            }
        }
    }
}

// ---------------- sparse attention: pairwise-merged online softmax, __expf --------
__global__ void k_attn() {
    int n = blockIdx.x;
    int warp = threadIdx.x >> 5;
    int lane = threadIdx.x & 31;
    int beg = g_rowptr[n], end = g_rowptr[n + 1];
    const float scale = 0.08838834764831845f;   // 1/sqrt(128)
    int hoff = warp * DH + lane * 4;
    uint2 qu = *(const uint2*)&g_qkv16[(size_t)n * 1536 + hoff];
    float2 q01 = __half22float2(*(__half2*)&qu.x);
    float2 q23 = __half22float2(*(__half2*)&qu.y);
    float m = -INFINITY, s = 0.0f;
    float a0 = 0.f, a1 = 0.f, a2 = 0.f, a3 = 0.f;
    int koff = hoff + 512;
    int e = beg;
    for (; e + 2 <= end; e += 2) {
        int d0 = g_csrdst[e], d1 = g_csrdst[e + 1];
        const __half* r0 = g_qkv16 + (size_t)d0 * 1536 + koff;
        const __half* r1 = g_qkv16 + (size_t)d1 * 1536 + koff;
        uint2 k0u = *(const uint2*)r0;
        uint2 k1u = *(const uint2*)r1;
        uint2 v0u = *(const uint2*)(r0 + 512);
        uint2 v1u = *(const uint2*)(r1 + 512);
        float2 k01 = __half22float2(*(__half2*)&k0u.x);
        float2 k23 = __half22float2(*(__half2*)&k0u.y);
        float p0 = q01.x * k01.x + q01.y * k01.y + q23.x * k23.x + q23.y * k23.y;
        float2 l01 = __half22float2(*(__half2*)&k1u.x);
        float2 l23 = __half22float2(*(__half2*)&k1u.y);
        float p1 = q01.x * l01.x + q01.y * l01.y + q23.x * l23.x + q23.y * l23.y;
        #pragma unroll
        for (int o = 16; o; o >>= 1) {
            p0 += __shfl_xor_sync(0xffffffffu, p0, o);
            p1 += __shfl_xor_sync(0xffffffffu, p1, o);
        }
        p0 *= scale; p1 *= scale;
        float mn = fmaxf(m, fmaxf(p0, p1));
        float corr = __expf(m - mn);
        float w0 = __expf(p0 - mn);
        float w1 = __expf(p1 - mn);
        float2 v01 = __half22float2(*(__half2*)&v0u.x);
        float2 v23 = __half22float2(*(__half2*)&v0u.y);
        float2 u01 = __half22float2(*(__half2*)&v1u.x);
        float2 u23 = __half22float2(*(__half2*)&v1u.y);
        s = s * corr + w0 + w1;
        a0 = fmaf(w0, v01.x, fmaf(w1, u01.x, a0 * corr));
        a1 = fmaf(w0, v01.y, fmaf(w1, u01.y, a1 * corr));
        a2 = fmaf(w0, v23.x, fmaf(w1, u23.x, a2 * corr));
        a3 = fmaf(w0, v23.y, fmaf(w1, u23.y, a3 * corr));
        m = mn;
    }
    if (e < end) {
        int d = g_csrdst[e];
        const __half* r0 = g_qkv16 + (size_t)d * 1536 + koff;
        uint2 ku = *(const uint2*)r0;
        uint2 vu = *(const uint2*)(r0 + 512);
        float2 k01 = __half22float2(*(__half2*)&ku.x);
        float2 k23 = __half22float2(*(__half2*)&ku.y);
        float p = q01.x * k01.x + q01.y * k01.y + q23.x * k23.x + q23.y * k23.y;
        #pragma unroll
        for (int o = 16; o; o >>= 1) p += __shfl_xor_sync(0xffffffffu, p, o);
        p *= scale;
        float mn = fmaxf(m, p);
        float corr = __expf(m - mn);
        float w = __expf(p - mn);
        float2 v01 = __half22float2(*(__half2*)&vu.x);
        float2 v23 = __half22float2(*(__half2*)&vu.y);
        s = s * corr + w;
        a0 = fmaf(w, v01.x, a0 * corr);
        a1 = fmaf(w, v01.y, a1 * corr);
        a2 = fmaf(w, v23.x, a2 * corr);
        a3 = fmaf(w, v23.y, a3 * corr);
        m = mn;
    }
    float inv = (end > beg) ? (1.0f / s) : 0.0f;
    __half2 h01 = __floats2half2_rn(a0 * inv, a1 * inv);
    __half2 h23 = __floats2half2_rn(a2 * inv, a3 * inv);
    *(uint2*)(g_attn16 + (size_t)n * DIM + hoff) =
        make_uint2(*(uint32_t*)&h01, *(uint32_t*)&h23);
}

// ---------------- host ----------------
extern "C" void kernel_launch(void* const* d_in, const int* in_sizes, int n_in,
                              void* d_out, int out_size) {
    const float* x_in  = (const float*)d_in[0];
    const int*   edge  = (const int*)d_in[1];
    const float* noise = (const float*)d_in[2];
    const float* f_w1 = (const float*)d_in[3];
    const float* f_b1 = (const float*)d_in[4];
    const float* f_w2 = (const float*)d_in[5];
    const float* f_b2 = (const float*)d_in[6];
    const float* s1_w = (const float*)d_in[7];
    const float* s1_b = (const float*)d_in[8];
    const float* b1_w = (const float*)d_in[9];
    const float* b1_b = (const float*)d_in[10];
    const float* wq = (const float*)d_in[11];
    const float* bq = (const float*)d_in[12];
    const float* wk = (const float*)d_in[13];
    const float* bk = (const float*)d_in[14];
    const float* wv = (const float*)d_in[15];
    const float* bv = (const float*)d_in[16];
    const float* wo = (const float*)d_in[17];
    const float* bo = (const float*)d_in[18];
    const float* s2_w = (const float*)d_in[19];
    const float* s2_b = (const float*)d_in[20];
    const float* b2_w = (const float*)d_in[21];
    const float* b2_b = (const float*)d_in[22];
    const float* m_w1 = (const float*)d_in[23];
    const float* m_b1 = (const float*)d_in[24];
    const float* m_w2 = (const float*)d_in[25];
    const float* m_b2 = (const float*)d_in[26];

    float* x = (float*)d_out;

    static bool init_done = false;
    static cudaStream_t s1;
    static cudaEvent_t evFork, evTab, evPrep, evCsr;
    if (!init_done) {
        cudaFuncSetAttribute(k_gemm_hmma, cudaFuncAttributeMaxDynamicSharedMemorySize,
                             GEMM_SMEM);
        cudaFuncSetAttribute(k_cln_fused, cudaFuncAttributeMaxDynamicSharedMemorySize,
                             CLN_SMEM);
        cudaStreamCreateWithFlags(&s1, cudaStreamNonBlocking);
        cudaEventCreateWithFlags(&evFork, cudaEventDisableTiming);
        cudaEventCreateWithFlags(&evTab, cudaEventDisableTiming);
        cudaEventCreateWithFlags(&evPrep, cudaEventDisableTiming);
        cudaEventCreateWithFlags(&evCsr, cudaEventDisableTiming);
        init_done = true;
    }

    __half *qkv16, *yp16, *ap16, *hp16;
    float *bqkv;
    cudaGetSymbolAddress((void**)&qkv16, g_qkv16);
    cudaGetSymbolAddress((void**)&yp16, g_y16);
    cudaGetSymbolAddress((void**)&ap16, g_attn16);
    cudaGetSymbolAddress((void**)&hp16, g_h16);
    cudaGetSymbolAddress((void**)&bqkv, g_bqkv);

    // ---- fork side stream for setup work (capture-legal fork/join) ----
    cudaEventRecord(evFork, 0);
    cudaStreamWaitEvent(s1, evFork, 0);

    // s1: FiLM tables, weight prep, CSR build
    k_film_tab<<<(32 * 8192 + 4 * 1536 + 255) / 256, 256, 0, s1>>>(
        s1_w, s1_b, b1_w, b1_b, s2_w, s2_b, b2_w, b2_b, bq, bk, bv);
    cudaEventRecord(evTab, s1);
    k_prep_w<<<dim3(16, 16, 24), dim3(32, 8), 0, s1>>>(wq, wk, wv, wo, m_w1, m_w2);
    cudaEventRecord(evPrep, s1);
    k_zero_deg<<<(N_NODES + 255) / 256, 256, 0, s1>>>();
    k_count_deg<<<(N_EDGES + 255) / 256, 256, 0, s1>>>(edge);
    k_scan_deg<<<1, 1024, 0, s1>>>();
    k_scatter_edges<<<(N_EDGES + 255) / 256, 256, 0, s1>>>(edge);
    cudaEventRecord(evCsr, s1);

    // s0: conditioning (independent of s1 work)
    k_cond<<<(N_NODES + 127) / 128, 128>>>(noise, f_w1, f_b1, f_w2, f_b2);

    const int CGRID = (N_NODES + 127) / 128;   // 321
    const int MROWS = (N_NODES + 127) / 128;
    dim3 gq(12, MROWS);
    dim3 gg(4, MROWS);
    bool waited_tab = false, waited_prep = false, waited_csr = false;
    for (int b = 0; b < NB; b++) {
        const size_t bOff = (size_t)b * DIM;
        const int slot = b * 6;
        const float* xr = (b == 0) ? x_in : x;

        if (!waited_tab) { cudaStreamWaitEvent(0, evTab, 0); waited_tab = true; }
        k_cln_fused<<<CGRID, 512, CLN_SMEM>>>(xr, b * 2048 + 0);
        if (!waited_prep) { cudaStreamWaitEvent(0, evPrep, 0); waited_prep = true; }
        k_gemm_hmma<<<gq, 256, GEMM_SMEM>>>(yp16, slot, bqkv + b * 1536, nullptr,
                                            nullptr, qkv16, 1536, N_NODES, 4);
        if (!waited_csr) { cudaStreamWaitEvent(0, evCsr, 0); waited_csr = true; }
        k_attn<<<N_NODES, 128>>>();
        k_gemm_hmma<<<gg, 256, GEMM_SMEM>>>(ap16, slot + 3, bo + bOff, xr, x,
                                            nullptr, 512, N_NODES, 2);
        k_cln_fused<<<CGRID, 512, CLN_SMEM>>>(x, b * 2048 + 1024);
        k_gemm_hmma<<<gg, 256, GEMM_SMEM>>>(yp16, slot + 4, m_b1 + bOff, nullptr,
                                            nullptr, hp16, 512, N_NODES, 5);
        k_gemm_hmma<<<gg, 256, GEMM_SMEM>>>(hp16, slot + 5, m_b2 + bOff, x, x,
                                            nullptr, 512, N_NODES, 2);
    }
}